// round 2
// baseline (speedup 1.0000x reference)
#include <cuda_runtime.h>
#include <math.h>

// Problem constants (fixed-shape problem: B=2048, D=768, P=B*NP=16384)
#define DIM        768
#define MAX_B      2048
#define MAX_P      16384
#define ALPHA_C    2.6f
#define OPTRANK_C  1.0f
#define SIGMA_C    1.8f

// Scratch (allocations are forbidden; __device__ globals are the sanctioned path)
__device__ float g_scores[(size_t)MAX_B * MAX_P];   // 134 MB
__device__ float g_loss[MAX_B];

// ---------------------------------------------------------------------------
// Kernel 1: scores[M,N] = A[M,K] * B[N,K]^T   (both K-major / "NT" gemm)
// 128x128 block tile, BK=16, 8x8 per thread, 256 threads.
// ---------------------------------------------------------------------------
#define BM 128
#define BN 128
#define BK 16
#define TM 8
#define TN 8

__global__ __launch_bounds__(256, 2)
void gemm_nt_kernel(const float* __restrict__ A, const float* __restrict__ B,
                    int M, int N, int K)
{
    __shared__ float As[BK][BM];
    __shared__ float Bs[BK][BN];

    const int tid = threadIdx.x;
    const int tx  = tid & 15;          // 0..15  (N direction)
    const int ty  = tid >> 4;          // 0..15  (M direction)
    const int m0  = blockIdx.y * BM;
    const int n0  = blockIdx.x * BN;

    float acc[TM][TN];
#pragma unroll
    for (int i = 0; i < TM; i++)
#pragma unroll
        for (int j = 0; j < TN; j++) acc[i][j] = 0.0f;

    // Each thread loads 2 float4 from A-tile and 2 from B-tile per K-step.
    // Tile is BM rows x BK cols = 128*16 floats = 512 float4.
    for (int k0 = 0; k0 < K; k0 += BK) {
#pragma unroll
        for (int it = 0; it < 2; it++) {
            int idx  = tid + it * 256;       // 0..511
            int row  = idx >> 2;             // 0..127
            int c4   = idx & 3;              // which float4 in the row (BK/4=4)
            float4 va = *(const float4*)&A[(size_t)(m0 + row) * K + k0 + c4 * 4];
            As[c4 * 4 + 0][row] = va.x;
            As[c4 * 4 + 1][row] = va.y;
            As[c4 * 4 + 2][row] = va.z;
            As[c4 * 4 + 3][row] = va.w;
            float4 vb = *(const float4*)&B[(size_t)(n0 + row) * K + k0 + c4 * 4];
            Bs[c4 * 4 + 0][row] = vb.x;
            Bs[c4 * 4 + 1][row] = vb.y;
            Bs[c4 * 4 + 2][row] = vb.z;
            Bs[c4 * 4 + 3][row] = vb.w;
        }
        __syncthreads();

#pragma unroll
        for (int kk = 0; kk < BK; kk++) {
            float a[TM], b[TN];
            // vector loads from smem
            *(float4*)&a[0] = *(const float4*)&As[kk][ty * TM + 0];
            *(float4*)&a[4] = *(const float4*)&As[kk][ty * TM + 4];
            *(float4*)&b[0] = *(const float4*)&Bs[kk][tx * TN + 0];
            *(float4*)&b[4] = *(const float4*)&Bs[kk][tx * TN + 4];
#pragma unroll
            for (int i = 0; i < TM; i++)
#pragma unroll
                for (int j = 0; j < TN; j++)
                    acc[i][j] = fmaf(a[i], b[j], acc[i][j]);
        }
        __syncthreads();
    }

    // store
#pragma unroll
    for (int i = 0; i < TM; i++) {
        size_t r = (size_t)(m0 + ty * TM + i) * N + n0 + tx * TN;
        float4 v0 = make_float4(acc[i][0], acc[i][1], acc[i][2], acc[i][3]);
        float4 v1 = make_float4(acc[i][4], acc[i][5], acc[i][6], acc[i][7]);
        *(float4*)&g_scores[r + 0] = v0;
        *(float4*)&g_scores[r + 4] = v1;
    }
}

// ---------------------------------------------------------------------------
// Kernel 2: per-row stats. One block (256 threads) per row.
//   rank = #{s_j > s_t} + #{s_j == s_t && j < t}   (stable descending argsort)
//   loss_i = (max + log(sum exp(x - max)) - s_t) * (1 + ALPHA*exp(-(r-1)^2/(2*sig^2)))
// ---------------------------------------------------------------------------
__global__ __launch_bounds__(256)
void row_stats_kernel(const int* __restrict__ np_ptr, int N)
{
    const int i   = blockIdx.x;
    const int tid = threadIdx.x;
    const float* __restrict__ row = g_scores + (size_t)i * N;
    const int t  = i * np_ptr[0];
    const float st = __ldg(&row[t]);

    __shared__ float s_f[256];
    __shared__ int   s_i[256];

    // pass 1: max + rank count
    float m   = -INFINITY;
    int   cnt = 0;
    const float4* r4 = (const float4*)row;
    const int n4 = N >> 2;
    for (int idx = tid; idx < n4; idx += 256) {
        float4 v = __ldg(&r4[idx]);
        m = fmaxf(m, fmaxf(fmaxf(v.x, v.y), fmaxf(v.z, v.w)));
        int j = idx << 2;
        cnt += (v.x > st) || (v.x == st && (j + 0) < t);
        cnt += (v.y > st) || (v.y == st && (j + 1) < t);
        cnt += (v.z > st) || (v.z == st && (j + 2) < t);
        cnt += (v.w > st) || (v.w == st && (j + 3) < t);
    }
    s_f[tid] = m;
    s_i[tid] = cnt;
    __syncthreads();
#pragma unroll
    for (int off = 128; off > 0; off >>= 1) {
        if (tid < off) {
            s_f[tid] = fmaxf(s_f[tid], s_f[tid + off]);
            s_i[tid] += s_i[tid + off];
        }
        __syncthreads();
    }
    const float gmax = s_f[0];
    const int   rank = s_i[0];
    __syncthreads();

    // pass 2: sum of exp(x - max)
    float s = 0.0f;
    for (int idx = tid; idx < n4; idx += 256) {
        float4 v = __ldg(&r4[idx]);
        s += __expf(v.x - gmax) + __expf(v.y - gmax)
           + __expf(v.z - gmax) + __expf(v.w - gmax);
    }
    s_f[tid] = s;
    __syncthreads();
#pragma unroll
    for (int off = 128; off > 0; off >>= 1) {
        if (tid < off) s_f[tid] += s_f[tid + off];
        __syncthreads();
    }

    if (tid == 0) {
        float raw = (gmax + logf(s_f[0])) - st;   // -log_softmax[target]
        float dr  = (float)rank - OPTRANK_C;
        float w   = 1.0f + ALPHA_C * expf(-(dr * dr) / (2.0f * SIGMA_C * SIGMA_C));
        g_loss[i] = raw * w;
    }
}

// ---------------------------------------------------------------------------
// Kernel 3: deterministic mean over B losses -> d_out[0]
// ---------------------------------------------------------------------------
__global__ __launch_bounds__(256)
void final_reduce_kernel(float* __restrict__ out, int B)
{
    __shared__ float s_f[256];
    const int tid = threadIdx.x;
    float s = 0.0f;
    for (int i = tid; i < B; i += 256) s += g_loss[i];
    s_f[tid] = s;
    __syncthreads();
#pragma unroll
    for (int off = 128; off > 0; off >>= 1) {
        if (tid < off) s_f[tid] += s_f[tid + off];
        __syncthreads();
    }
    if (tid == 0) out[0] = s_f[0] / (float)B;
}

// ---------------------------------------------------------------------------
extern "C" void kernel_launch(void* const* d_in, const int* in_sizes, int n_in,
                              void* d_out, int out_size)
{
    const float* q  = (const float*)d_in[0];   // [B, D]
    const float* p  = (const float*)d_in[1];   // [B*NP, D]
    const int*   np = (const int*)d_in[2];     // scalar n_passages (device)

    const int B = in_sizes[0] / DIM;           // 2048
    const int P = in_sizes[1] / DIM;           // 16384

    dim3 ggrid(P / BN, B / BM);
    gemm_nt_kernel<<<ggrid, 256>>>(q, p, B, P, DIM);
    row_stats_kernel<<<B, 256>>>(np, P);
    final_reduce_kernel<<<1, 256>>>((float*)d_out, B);
}

// round 4
// speedup vs baseline: 3.3912x; 3.3912x over previous
#include <cuda_runtime.h>
#include <math.h>
#include <stdint.h>

// ---------------------------------------------------------------------------
// Problem constants (fixed shape: B=2048, D=768, P=B*NP=16384)
// ---------------------------------------------------------------------------
#define DIM        768
#define MAX_B      2048
#define MAX_P      16384
#define ALPHA_C    2.6f
#define OPTRANK_C  1.0f
#define SIGMA_C    1.8f

__device__ float g_scores[(size_t)MAX_B * MAX_P];   // 134 MB scratch
__device__ float g_loss[MAX_B];

// ---------------------------------------------------------------------------
// GEMM config: scores[M,N] = A[M,K] * B[N,K]^T  via mma.sync m16n8k8 tf32
// CTA 128x128, BK=32, 8 warps (2 M x 4 N), warp tile 64x32, double buffer.
// ---------------------------------------------------------------------------
#define BM 128
#define BN 128
#define BK 32
#define KSTAGES (DIM / BK)          // 24
#define ROW_STRIDE 36               // floats per smem row (32 + 4 pad, conflict-free frags)
#define STAGE_FLOATS ((BM + BN) * ROW_STRIDE)   // 9216 floats = 36864 B
#define SMEM_BYTES (2 * STAGE_FLOATS * 4)       // 73728 B

__device__ __forceinline__ void cp_async16(uint32_t saddr, const void* gaddr) {
    asm volatile("cp.async.cg.shared.global [%0], [%1], 16;"
                 :: "r"(saddr), "l"(gaddr) : "memory");
}

__device__ __forceinline__ uint32_t smem_u32(const void* p) {
    uint32_t a;
    asm("{ .reg .u64 t; cvta.to.shared.u64 t, %1; cvt.u32.u64 %0, t; }"
        : "=r"(a) : "l"(p));
    return a;
}

__device__ __forceinline__ void mma_tf32(float c[4], const uint32_t a[4],
                                         const uint32_t b[2]) {
    asm volatile(
        "mma.sync.aligned.m16n8k8.row.col.f32.tf32.tf32.f32 "
        "{%0,%1,%2,%3}, {%4,%5,%6,%7}, {%8,%9}, {%0,%1,%2,%3};"
        : "+f"(c[0]), "+f"(c[1]), "+f"(c[2]), "+f"(c[3])
        : "r"(a[0]), "r"(a[1]), "r"(a[2]), "r"(a[3]), "r"(b[0]), "r"(b[1]));
}

__global__ __launch_bounds__(256, 2)
void gemm_tc_kernel(const float* __restrict__ A, const float* __restrict__ B)
{
    extern __shared__ float smem[];
    const uint32_t smem_b = smem_u32(smem);

    const int tid = threadIdx.x;
    const int wid = tid >> 5;
    const int lid = tid & 31;
    const int g   = lid >> 2;        // groupID (0..7)
    const int tig = lid & 3;         // threadID_in_group (0..3)
    const int wm  = wid >> 2;        // 0..1  (M)
    const int wn  = wid & 3;         // 0..3  (N)
    const int m0  = blockIdx.y * BM;
    const int n0  = blockIdx.x * BN;

    float acc[4][4][4];
#pragma unroll
    for (int mt = 0; mt < 4; mt++)
#pragma unroll
        for (int nt = 0; nt < 4; nt++)
#pragma unroll
            for (int r = 0; r < 4; r++) acc[mt][nt][r] = 0.0f;

    // ---- stage loader: 2048 x 16B cp.async, 8 per thread ----
    auto load_stage = [&](int s) {
        const int slot = s & 1;
        const int k0 = s * BK;
        const uint32_t sbase = smem_b + slot * (STAGE_FLOATS * 4);
#pragma unroll
        for (int i = 0; i < 8; i++) {
            int c = i * 256 + tid;                  // 0..2047
            if (c < 1024) {                         // A: 128 rows x 8 chunks
                int row = c >> 3, ch = c & 7;
                cp_async16(sbase + (row * ROW_STRIDE + ch * 4) * 4,
                           A + (size_t)(m0 + row) * DIM + k0 + ch * 4);
            } else {                                // B: 128 rows x 8 chunks
                int cb = c - 1024;
                int row = cb >> 3, ch = cb & 7;
                cp_async16(sbase + ((BM + row) * ROW_STRIDE + ch * 4) * 4,
                           B + (size_t)(n0 + row) * DIM + k0 + ch * 4);
            }
        }
        asm volatile("cp.async.commit_group;" ::: "memory");
    };

    load_stage(0);

    for (int s = 0; s < KSTAGES; s++) {
        if (s + 1 < KSTAGES) {
            load_stage(s + 1);
            asm volatile("cp.async.wait_group 1;" ::: "memory");
        } else {
            asm volatile("cp.async.wait_group 0;" ::: "memory");
        }
        __syncthreads();

        const float* As = smem + (s & 1) * STAGE_FLOATS;
        const float* Bs = As + BM * ROW_STRIDE;
        const float* aw = As + (wm * 64) * ROW_STRIDE;          // warp A base
        const float* bw = Bs + (wn * 32) * ROW_STRIDE;          // warp B base

#pragma unroll
        for (int ks = 0; ks < 4; ks++) {
            const int kk = ks * 8;
            uint32_t af[4][4];
#pragma unroll
            for (int mt = 0; mt < 4; mt++) {
                const float* ap = aw + (mt * 16) * ROW_STRIDE + kk;
                af[mt][0] = __float_as_uint(ap[(g)     * ROW_STRIDE + tig]);
                af[mt][1] = __float_as_uint(ap[(g + 8) * ROW_STRIDE + tig]);
                af[mt][2] = __float_as_uint(ap[(g)     * ROW_STRIDE + tig + 4]);
                af[mt][3] = __float_as_uint(ap[(g + 8) * ROW_STRIDE + tig + 4]);
            }
            uint32_t bf[4][2];
#pragma unroll
            for (int nt = 0; nt < 4; nt++) {
                const float* bp = bw + (nt * 8 + g) * ROW_STRIDE + kk;
                bf[nt][0] = __float_as_uint(bp[tig]);
                bf[nt][1] = __float_as_uint(bp[tig + 4]);
            }
#pragma unroll
            for (int mt = 0; mt < 4; mt++)
#pragma unroll
                for (int nt = 0; nt < 4; nt++)
                    mma_tf32(acc[mt][nt], af[mt], bf[nt]);
        }
        __syncthreads();
    }

    // ---- epilogue: float2 stores ----
#pragma unroll
    for (int mt = 0; mt < 4; mt++) {
#pragma unroll
        for (int nt = 0; nt < 4; nt++) {
            const int row = m0 + wm * 64 + mt * 16 + g;
            const int col = n0 + wn * 32 + nt * 8 + tig * 2;
            float* o = g_scores + (size_t)row * MAX_P + col;
            *(float2*)o = make_float2(acc[mt][nt][0], acc[mt][nt][1]);
            *(float2*)(o + (size_t)8 * MAX_P)
                = make_float2(acc[mt][nt][2], acc[mt][nt][3]);
        }
    }
}

// ---------------------------------------------------------------------------
// Kernel 2: per-row stats (rank / max / logsumexp / weighted CE)
// ---------------------------------------------------------------------------
__global__ __launch_bounds__(256)
void row_stats_kernel(const int* __restrict__ np_ptr, int N)
{
    const int i   = blockIdx.x;
    const int tid = threadIdx.x;
    const float* __restrict__ row = g_scores + (size_t)i * N;
    const int t  = i * np_ptr[0];
    const float st = __ldg(&row[t]);

    __shared__ float s_f[256];
    __shared__ int   s_i[256];

    float m   = -INFINITY;
    int   cnt = 0;
    const float4* r4 = (const float4*)row;
    const int n4 = N >> 2;
    for (int idx = tid; idx < n4; idx += 256) {
        float4 v = __ldg(&r4[idx]);
        m = fmaxf(m, fmaxf(fmaxf(v.x, v.y), fmaxf(v.z, v.w)));
        int j = idx << 2;
        cnt += (v.x > st) || (v.x == st && (j + 0) < t);
        cnt += (v.y > st) || (v.y == st && (j + 1) < t);
        cnt += (v.z > st) || (v.z == st && (j + 2) < t);
        cnt += (v.w > st) || (v.w == st && (j + 3) < t);
    }
    s_f[tid] = m;
    s_i[tid] = cnt;
    __syncthreads();
#pragma unroll
    for (int off = 128; off > 0; off >>= 1) {
        if (tid < off) {
            s_f[tid] = fmaxf(s_f[tid], s_f[tid + off]);
            s_i[tid] += s_i[tid + off];
        }
        __syncthreads();
    }
    const float gmax = s_f[0];
    const int   rank = s_i[0];
    __syncthreads();

    float s = 0.0f;
    for (int idx = tid; idx < n4; idx += 256) {
        float4 v = __ldg(&r4[idx]);
        s += __expf(v.x - gmax) + __expf(v.y - gmax)
           + __expf(v.z - gmax) + __expf(v.w - gmax);
    }
    s_f[tid] = s;
    __syncthreads();
#pragma unroll
    for (int off = 128; off > 0; off >>= 1) {
        if (tid < off) s_f[tid] += s_f[tid + off];
        __syncthreads();
    }

    if (tid == 0) {
        float raw = (gmax + logf(s_f[0])) - st;
        float dr  = (float)rank - OPTRANK_C;
        float w   = 1.0f + ALPHA_C * expf(-(dr * dr) / (2.0f * SIGMA_C * SIGMA_C));
        g_loss[i] = raw * w;
    }
}

// ---------------------------------------------------------------------------
// Kernel 3: deterministic mean -> d_out[0]
// ---------------------------------------------------------------------------
__global__ __launch_bounds__(256)
void final_reduce_kernel(float* __restrict__ out, int B)
{
    __shared__ float s_f[256];
    const int tid = threadIdx.x;
    float s = 0.0f;
    for (int i = tid; i < B; i += 256) s += g_loss[i];
    s_f[tid] = s;
    __syncthreads();
#pragma unroll
    for (int off = 128; off > 0; off >>= 1) {
        if (tid < off) s_f[tid] += s_f[tid + off];
        __syncthreads();
    }
    if (tid == 0) out[0] = s_f[0] / (float)B;
}

// ---------------------------------------------------------------------------
extern "C" void kernel_launch(void* const* d_in, const int* in_sizes, int n_in,
                              void* d_out, int out_size)
{
    const float* q  = (const float*)d_in[0];   // [B, D]
    const float* p  = (const float*)d_in[1];   // [B*NP, D]
    const int*   np = (const int*)d_in[2];

    const int B = in_sizes[0] / DIM;           // 2048
    const int P = in_sizes[1] / DIM;           // 16384

    cudaFuncSetAttribute(gemm_tc_kernel,
                         cudaFuncAttributeMaxDynamicSharedMemorySize, SMEM_BYTES);

    dim3 ggrid(P / BN, B / BM);                // (128, 16)
    gemm_tc_kernel<<<ggrid, 256, SMEM_BYTES>>>(q, p);
    row_stats_kernel<<<B, 256>>>(np, P);
    final_reduce_kernel<<<1, 256>>>((float*)d_out, B);
}